// round 1
// baseline (speedup 1.0000x reference)
#include <cuda_runtime.h>

// Erosion2D: out[b,y,x,c] = min_{dy,dx in [0,4)} x[y+dy-1, x+dx-1, c] - w[3-dy, 3-dx, c]
// (out-of-range input treated as +1e30, matching the reference's BIG padding)

#define BIGF 1e30f

constexpr int B = 8, H = 512, W = 512, C = 32;
constexpr int TY = 16, TX = 32;
constexpr int SR = TY + 3;                 // 19 smem rows
constexpr int SP = TX + 3;                 // 35 smem pixel-columns
constexpr int SMEM_FLOATS = SR * SP * C;   // 21280 floats = 85120 B
constexpr int THREADS = 256;

__global__ __launch_bounds__(THREADS, 2)
void erosion2d_kernel(const float* __restrict__ xin,
                      const float* __restrict__ wt,
                      float* __restrict__ out) {
    extern __shared__ float tile[];

    const int bx = blockIdx.x;          // x tile: 0..15
    const int by = blockIdx.y;          // y tile: 0..31
    const int b  = blockIdx.z;          // batch
    const int x0 = bx * TX;
    const int y0 = by * TY;
    const int tid = threadIdx.x;

    const float* xb = xin + (size_t)b * H * W * C;

    // ---------------- load halo tile into smem ----------------
    const bool interior = (bx > 0) & (bx < (W / TX - 1)) & (by > 0) & (by < (H / TY - 1));
    constexpr int LOADS = SR * SP * (C / 4);   // float4 loads: 5320

    if (interior) {
        #pragma unroll 4
        for (int i = tid; i < LOADS; i += THREADS) {
            int r   = i / (SP * (C / 4));
            int rem = i - r * (SP * (C / 4));
            int p   = rem >> 3;            // pixel in row (C/4 == 8)
            int q   = rem & 7;             // channel quad
            int gy = y0 - 1 + r;
            int gx = x0 - 1 + p;
            float4 v = *(const float4*)(xb + ((size_t)gy * W + gx) * C + q * 4);
            *(float4*)(tile + (r * SP + p) * C + q * 4) = v;
        }
    } else {
        #pragma unroll 4
        for (int i = tid; i < LOADS; i += THREADS) {
            int r   = i / (SP * (C / 4));
            int rem = i - r * (SP * (C / 4));
            int p   = rem >> 3;
            int q   = rem & 7;
            int gy = y0 - 1 + r;
            int gx = x0 - 1 + p;
            float4 v;
            if (gy >= 0 && gy < H && gx >= 0 && gx < W) {
                v = *(const float4*)(xb + ((size_t)gy * W + gx) * C + q * 4);
            } else {
                v = make_float4(BIGF, BIGF, BIGF, BIGF);
            }
            *(float4*)(tile + (r * SP + p) * C + q * 4) = v;
        }
    }
    __syncthreads();

    // ---------------- compute ----------------
    // thread -> (output row ty in tile, channel pair cp)
    const int cp = tid & 15;        // 0..15 -> channels 2*cp, 2*cp+1
    const int ty = tid >> 4;        // 0..15
    const int c0 = cp * 2;

    // weights: wr[d][k] = w[3-k][3-d][c0..c0+1]
    float2 wr[4][4];
    #pragma unroll
    for (int d = 0; d < 4; d++) {
        #pragma unroll
        for (int k = 0; k < 4; k++) {
            const float* wp = wt + ((3 - k) * 4 + (3 - d)) * C + c0;
            wr[d][k] = make_float2(wp[0], wp[1]);
        }
    }

    float* op = out + (((size_t)(b * H + y0 + ty) * W + x0) * C) + c0;

    // ring registers:
    //   q0a = c0(s-3), q0b = c0(s-2), q0c = c0(s-1)   (after step s-1)
    //   q1a = c1(s-2), q1b = c1(s-1)
    //   q2a = c2(s-1)
    float2 q0a, q0b, q0c, q1a, q1b, q2a;
    q0a = q0b = q0c = q1a = q1b = q2a = make_float2(BIGF, BIGF);

    const int rowbase = ty * SP;

    #pragma unroll
    for (int s = 0; s < SP; s++) {
        // 4 input rows of smem column s (this thread's channel pair)
        float2 r0 = *(const float2*)(tile + ((rowbase) + s) * C + c0);
        float2 r1 = *(const float2*)(tile + ((rowbase + SP) + s) * C + c0);
        float2 r2 = *(const float2*)(tile + ((rowbase + 2 * SP) + s) * C + c0);
        float2 r3 = *(const float2*)(tile + ((rowbase + 3 * SP) + s) * C + c0);

        // column pass: cd[d] = min_k (r_k - wr[d][k])
        float2 cd[4];
        #pragma unroll
        for (int d = 0; d < 4; d++) {
            float ax = fminf(fminf(r0.x - wr[d][0].x, r1.x - wr[d][1].x),
                             fminf(r2.x - wr[d][2].x, r3.x - wr[d][3].x));
            float ay = fminf(fminf(r0.y - wr[d][0].y, r1.y - wr[d][1].y),
                             fminf(r2.y - wr[d][2].y, r3.y - wr[d][3].y));
            cd[d] = make_float2(ax, ay);
        }

        // horizontal combine: out(j=s-3) = min(c0(j), c1(j+1), c2(j+2), c3(j+3))
        if (s >= 3) {
            float ox = fminf(fminf(q0a.x, q1a.x), fminf(q2a.x, cd[3].x));
            float oy = fminf(fminf(q0a.y, q1a.y), fminf(q2a.y, cd[3].y));
            *(float2*)(op + (size_t)(s - 3) * C) = make_float2(ox, oy);
        }

        // shift rings
        q0a = q0b; q0b = q0c; q0c = cd[0];
        q1a = q1b; q1b = cd[1];
        q2a = cd[2];
    }
}

extern "C" void kernel_launch(void* const* d_in, const int* in_sizes, int n_in,
                              void* d_out, int out_size) {
    const float* x = (const float*)d_in[0];
    const float* w = (const float*)d_in[1];
    float* out = (float*)d_out;

    // dynamic smem > 48KB requires opt-in; idempotent, capture-safe host call
    cudaFuncSetAttribute(erosion2d_kernel,
                         cudaFuncAttributeMaxDynamicSharedMemorySize,
                         SMEM_FLOATS * (int)sizeof(float));

    dim3 grid(W / TX, H / TY, B);   // 16 x 32 x 8 = 4096 blocks
    erosion2d_kernel<<<grid, THREADS, SMEM_FLOATS * sizeof(float)>>>(x, w, out);
}